// round 7
// baseline (speedup 1.0000x reference)
#include <cuda_runtime.h>
#include <cuda_bf16.h>
#include <math.h>
#include <stdint.h>

constexpr int Bsz  = 4;
constexpr int Fdim = 2048;
constexpr int Tdim = 2048;
constexpr int Hdim = 1024;
constexpr int NH   = 16;
constexpr int HS   = 64;

// ---------------------------------------------------------------------------
// bf16 split scratch (hi + lo), all in gmem
// ---------------------------------------------------------------------------
__device__ __nv_bfloat16 g_Xh[(size_t)16384 * 1024];
__device__ __nv_bfloat16 g_Xl[(size_t)16384 * 1024];
__device__ __nv_bfloat16 g_Wh[(size_t)3 * 1024 * 1024];
__device__ __nv_bfloat16 g_Wl[(size_t)3 * 1024 * 1024];
__device__ __nv_bfloat16 g_Qh[(size_t)Bsz * NH * Fdim * HS];
__device__ __nv_bfloat16 g_Ql[(size_t)Bsz * NH * Fdim * HS];
__device__ __nv_bfloat16 g_Kh[(size_t)Bsz * NH * Tdim * HS];
__device__ __nv_bfloat16 g_Kl[(size_t)Bsz * NH * Tdim * HS];
__device__ __nv_bfloat16 g_Vh[(size_t)Bsz * NH * Tdim * HS];
__device__ __nv_bfloat16 g_Vl[(size_t)Bsz * NH * Tdim * HS];

// ---------------------------------------------------------------------------
// helpers
// ---------------------------------------------------------------------------
__device__ __forceinline__ uint32_t smem_u32(const void* p) {
    return (uint32_t)__cvta_generic_to_shared(p);
}
__device__ __forceinline__ void ldsm_x4(uint32_t* r, uint32_t a) {
    asm volatile("ldmatrix.sync.aligned.m8n8.x4.shared.b16 {%0,%1,%2,%3}, [%4];"
                 : "=r"(r[0]), "=r"(r[1]), "=r"(r[2]), "=r"(r[3]) : "r"(a));
}
__device__ __forceinline__ void ldsm_x4t(uint32_t* r, uint32_t a) {
    asm volatile("ldmatrix.sync.aligned.m8n8.x4.trans.shared.b16 {%0,%1,%2,%3}, [%4];"
                 : "=r"(r[0]), "=r"(r[1]), "=r"(r[2]), "=r"(r[3]) : "r"(a));
}
__device__ __forceinline__ void mma16816(float* c, const uint32_t* a, const uint32_t* b) {
    asm volatile(
        "mma.sync.aligned.m16n8k16.row.col.f32.bf16.bf16.f32 "
        "{%0,%1,%2,%3}, {%4,%5,%6,%7}, {%8,%9}, {%0,%1,%2,%3};"
        : "+f"(c[0]), "+f"(c[1]), "+f"(c[2]), "+f"(c[3])
        : "r"(a[0]), "r"(a[1]), "r"(a[2]), "r"(a[3]), "r"(b[0]), "r"(b[1]));
}
__device__ __forceinline__ void split_pack2(float x, float y, uint32_t& hi, uint32_t& lo) {
    __nv_bfloat16 hx = __float2bfloat16_rn(x);
    __nv_bfloat16 hy = __float2bfloat16_rn(y);
    __nv_bfloat162 hp = __halves2bfloat162(hx, hy);
    hi = *reinterpret_cast<uint32_t*>(&hp);
    __nv_bfloat162 lp = __floats2bfloat162_rn(x - __bfloat162float(hx),
                                              y - __bfloat162float(hy));
    lo = *reinterpret_cast<uint32_t*>(&lp);
}
__device__ __forceinline__ void cp16(uint32_t s, const void* g) {
    asm volatile("cp.async.cg.shared.global [%0], [%1], 16;" :: "r"(s), "l"(g));
}
__device__ __forceinline__ void cp_commit() { asm volatile("cp.async.commit_group;"); }
template <int N> __device__ __forceinline__ void cp_wait() {
    asm volatile("cp.async.wait_group %0;" :: "n"(N));
}

// ---------------------------------------------------------------------------
// split pre-pass
// ---------------------------------------------------------------------------
__global__ __launch_bounds__(256) void split_kernel(
    const float* __restrict__ src, __nv_bfloat16* __restrict__ h,
    __nv_bfloat16* __restrict__ l)
{
    size_t i = ((size_t)blockIdx.x * 256 + threadIdx.x) * 4;
    float4 v = *(const float4*)(src + i);
    uint32_t h0, l0, h1, l1;
    split_pack2(v.x, v.y, h0, l0);
    split_pack2(v.z, v.w, h1, l1);
    uint2 hv = { h0, h1 }, lv = { l0, l1 };
    *(uint2*)(h + i) = hv;
    *(uint2*)(l + i) = lv;
}

// ---------------------------------------------------------------------------
// Projection GEMM: bf16 split, 3-stage cp.async pipeline, 1 barrier/iter.
// Block 128(M) x 128(N), K-step 32, 8 warps (warp tile 64x32).
// ---------------------------------------------------------------------------
struct ProjSmem {
    __nv_bfloat16 AsH[3][128][40];
    __nv_bfloat16 AsL[3][128][40];
    __nv_bfloat16 BsH[3][32][136];
    __nv_bfloat16 BsL[3][32][136];
};

__global__ __launch_bounds__(256, 2) void proj_kernel(
    const float* __restrict__ bq, const float* __restrict__ bk,
    const float* __restrict__ bv)
{
    extern __shared__ char smem_raw[];
    ProjSmem& sm = *reinterpret_cast<ProjSmem*>(smem_raw);

    const int z = blockIdx.z;
    const __nv_bfloat16* Ah = g_Xh + (z ? (size_t)8192 * 1024 : 0);
    const __nv_bfloat16* Al = g_Xl + (z ? (size_t)8192 * 1024 : 0);
    const __nv_bfloat16* Wh = g_Wh + (size_t)z * 1024 * 1024;
    const __nv_bfloat16* Wl = g_Wl + (size_t)z * 1024 * 1024;
    const float* bias = (z == 0) ? bq : (z == 1) ? bk : bv;
    __nv_bfloat16* outh = (z == 0) ? g_Qh : (z == 1) ? g_Kh : g_Vh;
    __nv_bfloat16* outl = (z == 0) ? g_Ql : (z == 1) ? g_Kl : g_Vl;
    const float scale = (z == 0) ? 0.125f : 1.0f;

    const int tid  = threadIdx.x;
    const int warp = tid >> 5;
    const int lane = tid & 31;
    const int g    = lane >> 2;
    const int tg   = lane & 3;

    const int m0 = blockIdx.y * 128;
    const int n0 = blockIdx.x * 128;
    const int wm = (warp >> 2) * 64;
    const int wn = (warp & 3) * 32;

    const int a_r = tid >> 1, a_c = (tid & 1) * 16;
    const int b_r = tid >> 3, b_c = (tid & 7) * 16;

    auto issue = [&](int st, int k0) {
        const __nv_bfloat16* gah = Ah + (size_t)(m0 + a_r) * 1024 + k0 + a_c;
        const __nv_bfloat16* gal = Al + (size_t)(m0 + a_r) * 1024 + k0 + a_c;
        cp16(smem_u32(&sm.AsH[st][a_r][a_c]),     gah);
        cp16(smem_u32(&sm.AsH[st][a_r][a_c + 8]), gah + 8);
        cp16(smem_u32(&sm.AsL[st][a_r][a_c]),     gal);
        cp16(smem_u32(&sm.AsL[st][a_r][a_c + 8]), gal + 8);
        const __nv_bfloat16* gbh = Wh + (size_t)(k0 + b_r) * 1024 + n0 + b_c;
        const __nv_bfloat16* gbl = Wl + (size_t)(k0 + b_r) * 1024 + n0 + b_c;
        cp16(smem_u32(&sm.BsH[st][b_r][b_c]),     gbh);
        cp16(smem_u32(&sm.BsH[st][b_r][b_c + 8]), gbh + 8);
        cp16(smem_u32(&sm.BsL[st][b_r][b_c]),     gbl);
        cp16(smem_u32(&sm.BsL[st][b_r][b_c + 8]), gbl + 8);
    };

    float acc[4][4][4] = {};

    issue(0, 0);  cp_commit();
    issue(1, 32); cp_commit();

    const int ar = wm + (lane & 15);
    const int acol = (lane >> 4) * 8;
    const int l7 = lane & 7;
    const int khalf = (lane >> 3) & 1;
    const int nhalf = lane >> 4;

    for (int it = 0; it < 32; it++) {
        if (it + 1 < 32) cp_wait<1>(); else cp_wait<0>();
        __syncthreads();
        if (it + 2 < 32) { issue((it + 2) % 3, (it + 2) * 32); cp_commit(); }
        const int st = it % 3;

#pragma unroll
        for (int kk = 0; kk < 32; kk += 16) {
            uint32_t bH[4][2], bL[4][2];
#pragma unroll
            for (int p = 0; p < 2; p++) {
                uint32_t r4[4];
                ldsm_x4t(r4, smem_u32(&sm.BsH[st][kk + khalf * 8 + l7][wn + p * 16 + nhalf * 8]));
                bH[2 * p][0] = r4[0]; bH[2 * p][1] = r4[1];
                bH[2 * p + 1][0] = r4[2]; bH[2 * p + 1][1] = r4[3];
                ldsm_x4t(r4, smem_u32(&sm.BsL[st][kk + khalf * 8 + l7][wn + p * 16 + nhalf * 8]));
                bL[2 * p][0] = r4[0]; bL[2 * p][1] = r4[1];
                bL[2 * p + 1][0] = r4[2]; bL[2 * p + 1][1] = r4[3];
            }
#pragma unroll
            for (int mi = 0; mi < 4; mi++) {
                uint32_t aH[4], aL[4];
                ldsm_x4(aH, smem_u32(&sm.AsH[st][ar + mi * 16][kk + acol]));
                ldsm_x4(aL, smem_u32(&sm.AsL[st][ar + mi * 16][kk + acol]));
#pragma unroll
                for (int ni = 0; ni < 4; ni++) {
                    mma16816(acc[mi][ni], aH, bH[ni]);
                    mma16816(acc[mi][ni], aH, bL[ni]);
                    mma16816(acc[mi][ni], aL, bH[ni]);
                }
            }
        }
    }

    // epilogue: bias, scale, split, permuted bf16 store
#pragma unroll
    for (int ni = 0; ni < 4; ni++) {
        const int col = n0 + wn + ni * 8 + tg * 2;
        const int head = col >> 6;
        const int d = col & 63;
        float2 b2 = *(const float2*)&bias[col];
#pragma unroll
        for (int mi = 0; mi < 4; mi++) {
#pragma unroll
            for (int half = 0; half < 2; half++) {
                int m  = m0 + wm + mi * 16 + g + half * 8;
                int bi = m >> 11, si = m & 2047;
                float x = (acc[mi][ni][2 * half]     + b2.x) * scale;
                float y = (acc[mi][ni][2 * half + 1] + b2.y) * scale;
                uint32_t hi, lo;
                split_pack2(x, y, hi, lo);
                size_t idx = (((size_t)bi * NH + head) * 2048 + si) * HS + d;
                *(uint32_t*)&outh[idx] = hi;
                *(uint32_t*)&outl[idx] = lo;
            }
        }
    }
}

// ---------------------------------------------------------------------------
// Flash attention: bf16 split, 3-stage cp.async K/V pipeline, 1 barrier/iter.
// Block 128 F-rows x 64 T-tile, 8 warps (one m16 band each).
// ---------------------------------------------------------------------------
struct AttnSmem {
    __nv_bfloat16 KH[3][64][72];
    __nv_bfloat16 KL[3][64][72];
    __nv_bfloat16 VH[3][64][72];
    __nv_bfloat16 VL[3][64][72];
};

__global__ __launch_bounds__(256, 2) void attn_kernel(
    const float* __restrict__ mask,   // [B, F, T]
    float* __restrict__ out)          // [B, F, NH, HS]
{
    extern __shared__ char smem_raw[];
    AttnSmem& sm = *reinterpret_cast<AttnSmem*>(smem_raw);

    const int tid  = threadIdx.x;
    const int warp = tid >> 5;
    const int lane = tid & 31;
    const int g    = lane >> 2;
    const int tg   = lane & 3;

    const int f0 = blockIdx.x * 128;
    const int n  = blockIdx.y;
    const int b  = blockIdx.z;
    const size_t hb = (size_t)b * NH + n;

    const __nv_bfloat16* Qh = g_Qh + (hb * Fdim + f0 + warp * 16) * HS;
    const __nv_bfloat16* Ql = g_Ql + (hb * Fdim + f0 + warp * 16) * HS;
    const __nv_bfloat16* Kh = g_Kh + hb * Tdim * HS;
    const __nv_bfloat16* Kl = g_Kl + hb * Tdim * HS;
    const __nv_bfloat16* Vh = g_Vh + hb * Tdim * HS;
    const __nv_bfloat16* Vl = g_Vl + hb * Tdim * HS;
    const float* Mw = mask + ((size_t)b * Fdim + f0 + warp * 16) * Tdim;

    // Q fragments direct from gmem (already scaled by 1/8)
    uint32_t qH[4][4], qL[4][4];
#pragma unroll
    for (int kc = 0; kc < 4; kc++) {
        qH[kc][0] = *(const uint32_t*)(Qh + (size_t)g * HS + kc * 16 + tg * 2);
        qH[kc][1] = *(const uint32_t*)(Qh + (size_t)(g + 8) * HS + kc * 16 + tg * 2);
        qH[kc][2] = *(const uint32_t*)(Qh + (size_t)g * HS + kc * 16 + 8 + tg * 2);
        qH[kc][3] = *(const uint32_t*)(Qh + (size_t)(g + 8) * HS + kc * 16 + 8 + tg * 2);
        qL[kc][0] = *(const uint32_t*)(Ql + (size_t)g * HS + kc * 16 + tg * 2);
        qL[kc][1] = *(const uint32_t*)(Ql + (size_t)(g + 8) * HS + kc * 16 + tg * 2);
        qL[kc][2] = *(const uint32_t*)(Ql + (size_t)g * HS + kc * 16 + 8 + tg * 2);
        qL[kc][3] = *(const uint32_t*)(Ql + (size_t)(g + 8) * HS + kc * 16 + 8 + tg * 2);
    }

    const int ld_r = tid >> 2;
    const int ld_c = (tid & 3) * 16;

    auto issue = [&](int st, int t0) {
        const size_t go = (size_t)(t0 + ld_r) * HS + ld_c;
        cp16(smem_u32(&sm.KH[st][ld_r][ld_c]),     Kh + go);
        cp16(smem_u32(&sm.KH[st][ld_r][ld_c + 8]), Kh + go + 8);
        cp16(smem_u32(&sm.KL[st][ld_r][ld_c]),     Kl + go);
        cp16(smem_u32(&sm.KL[st][ld_r][ld_c + 8]), Kl + go + 8);
        cp16(smem_u32(&sm.VH[st][ld_r][ld_c]),     Vh + go);
        cp16(smem_u32(&sm.VH[st][ld_r][ld_c + 8]), Vh + go + 8);
        cp16(smem_u32(&sm.VL[st][ld_r][ld_c]),     Vl + go);
        cp16(smem_u32(&sm.VL[st][ld_r][ld_c + 8]), Vl + go + 8);
    };

    float o[8][4] = {};
    float mrow0 = -1e30f, mrow1 = -1e30f, l0 = 0.f, l1 = 0.f;

    issue(0, 0);  cp_commit();
    issue(1, 64); cp_commit();

    const int l7 = lane & 7;
    const int half8 = (lane >> 3) & 1;
    const int quad  = lane >> 4;

    for (int it = 0; it < 32; it++) {
        const int t0 = it * 64;
        if (it + 1 < 32) cp_wait<1>(); else cp_wait<0>();
        __syncthreads();
        if (it + 2 < 32) { issue((it + 2) % 3, t0 + 128); cp_commit(); }
        const int st = it % 3;

        // S = Q K^T
        float s[8][4];
#pragma unroll
        for (int ni = 0; ni < 8; ni++)
            s[ni][0] = s[ni][1] = s[ni][2] = s[ni][3] = 0.f;

#pragma unroll
        for (int np = 0; np < 4; np++) {
            const int krow = np * 16 + quad * 8 + l7;
#pragma unroll
            for (int kc = 0; kc < 4; kc++) {
                uint32_t k4h[4], k4l[4];
                ldsm_x4(k4h, smem_u32(&sm.KH[st][krow][kc * 16 + half8 * 8]));
                ldsm_x4(k4l, smem_u32(&sm.KL[st][krow][kc * 16 + half8 * 8]));
                mma16816(s[2 * np],     qH[kc], k4h);
                mma16816(s[2 * np],     qH[kc], k4l);
                mma16816(s[2 * np],     qL[kc], k4h);
                mma16816(s[2 * np + 1], qH[kc], k4h + 2);
                mma16816(s[2 * np + 1], qH[kc], k4l + 2);
                mma16816(s[2 * np + 1], qL[kc], k4h + 2);
            }
        }

        // mask adder
#pragma unroll
        for (int ni = 0; ni < 8; ni++) {
            float2 mm0 = *(const float2*)&Mw[(size_t)g * Tdim + t0 + ni * 8 + tg * 2];
            float2 mm1 = *(const float2*)&Mw[(size_t)(g + 8) * Tdim + t0 + ni * 8 + tg * 2];
            s[ni][0] += (1.f - mm0.x) * (-10000.f);
            s[ni][1] += (1.f - mm0.y) * (-10000.f);
            s[ni][2] += (1.f - mm1.x) * (-10000.f);
            s[ni][3] += (1.f - mm1.y) * (-10000.f);
        }

        // online softmax
        float rmax0 = -1e30f, rmax1 = -1e30f;
#pragma unroll
        for (int ni = 0; ni < 8; ni++) {
            rmax0 = fmaxf(rmax0, fmaxf(s[ni][0], s[ni][1]));
            rmax1 = fmaxf(rmax1, fmaxf(s[ni][2], s[ni][3]));
        }
        rmax0 = fmaxf(rmax0, __shfl_xor_sync(0xffffffffu, rmax0, 1));
        rmax0 = fmaxf(rmax0, __shfl_xor_sync(0xffffffffu, rmax0, 2));
        rmax1 = fmaxf(rmax1, __shfl_xor_sync(0xffffffffu, rmax1, 1));
        rmax1 = fmaxf(rmax1, __shfl_xor_sync(0xffffffffu, rmax1, 2));

        float mnew0 = fmaxf(mrow0, rmax0);
        float mnew1 = fmaxf(mrow1, rmax1);
        float esc0 = __expf(mrow0 - mnew0);
        float esc1 = __expf(mrow1 - mnew1);
        mrow0 = mnew0;  mrow1 = mnew1;

        float rs0 = 0.f, rs1 = 0.f;
#pragma unroll
        for (int ni = 0; ni < 8; ni++) {
            s[ni][0] = __expf(s[ni][0] - mnew0);
            s[ni][1] = __expf(s[ni][1] - mnew0);
            s[ni][2] = __expf(s[ni][2] - mnew1);
            s[ni][3] = __expf(s[ni][3] - mnew1);
            rs0 += s[ni][0] + s[ni][1];
            rs1 += s[ni][2] + s[ni][3];
        }
        rs0 += __shfl_xor_sync(0xffffffffu, rs0, 1);
        rs0 += __shfl_xor_sync(0xffffffffu, rs0, 2);
        rs1 += __shfl_xor_sync(0xffffffffu, rs1, 1);
        rs1 += __shfl_xor_sync(0xffffffffu, rs1, 2);

        l0 = l0 * esc0 + rs0;
        l1 = l1 * esc1 + rs1;
#pragma unroll
        for (int di = 0; di < 8; di++) {
            o[di][0] *= esc0;  o[di][1] *= esc0;
            o[di][2] *= esc1;  o[di][3] *= esc1;
        }

        // O += P V
#pragma unroll
        for (int kc = 0; kc < 4; kc++) {
            uint32_t pH[4], pL[4];
            split_pack2(s[2 * kc][0],     s[2 * kc][1],     pH[0], pL[0]);
            split_pack2(s[2 * kc][2],     s[2 * kc][3],     pH[1], pL[1]);
            split_pack2(s[2 * kc + 1][0], s[2 * kc + 1][1], pH[2], pL[2]);
            split_pack2(s[2 * kc + 1][2], s[2 * kc + 1][3], pH[3], pL[3]);
            const int vrow = kc * 16 + half8 * 8 + l7;
#pragma unroll
            for (int dp = 0; dp < 4; dp++) {
                uint32_t v4h[4], v4l[4];
                ldsm_x4t(v4h, smem_u32(&sm.VH[st][vrow][dp * 16 + quad * 8]));
                ldsm_x4t(v4l, smem_u32(&sm.VL[st][vrow][dp * 16 + quad * 8]));
                mma16816(o[2 * dp],     pH, v4h);
                mma16816(o[2 * dp],     pH, v4l);
                mma16816(o[2 * dp],     pL, v4h);
                mma16816(o[2 * dp + 1], pH, v4h + 2);
                mma16816(o[2 * dp + 1], pH, v4l + 2);
                mma16816(o[2 * dp + 1], pL, v4h + 2);
            }
        }
    }

    // epilogue
    const float inv0 = 1.f / l0;
    const float inv1 = 1.f / l1;
    const int f = f0 + warp * 16 + g;
    float* orow0 = out + (((size_t)b * Fdim + f) * NH + n) * HS;
    float* orow1 = out + (((size_t)b * Fdim + f + 8) * NH + n) * HS;
#pragma unroll
    for (int di = 0; di < 8; di++) {
        float2 r0 = { o[di][0] * inv0, o[di][1] * inv0 };
        float2 r1 = { o[di][2] * inv1, o[di][3] * inv1 };
        *(float2*)&orow0[di * 8 + tg * 2] = r0;
        *(float2*)&orow1[di * 8 + tg * 2] = r1;
    }
}

// ---------------------------------------------------------------------------
extern "C" void kernel_launch(void* const* d_in, const int* in_sizes, int n_in,
                              void* d_out, int out_size)
{
    const float* from = (const float*)d_in[0];
    const float* to   = (const float*)d_in[1];
    const float* mask = (const float*)d_in[2];
    const float* Wq   = (const float*)d_in[3];
    const float* bq   = (const float*)d_in[4];
    const float* Wk   = (const float*)d_in[5];
    const float* bk   = (const float*)d_in[6];
    const float* Wv   = (const float*)d_in[7];
    const float* bv   = (const float*)d_in[8];
    float* out = (float*)d_out;

    cudaFuncSetAttribute(proj_kernel, cudaFuncAttributeMaxDynamicSharedMemorySize,
                         (int)sizeof(ProjSmem));
    cudaFuncSetAttribute(attn_kernel, cudaFuncAttributeMaxDynamicSharedMemorySize,
                         (int)sizeof(AttnSmem));

    __nv_bfloat16 *xh, *xl, *wh, *wl;
    cudaGetSymbolAddress((void**)&xh, g_Xh);
    cudaGetSymbolAddress((void**)&xl, g_Xl);
    cudaGetSymbolAddress((void**)&wh, g_Wh);
    cudaGetSymbolAddress((void**)&wl, g_Wl);

    split_kernel<<<8192, 256>>>(from, xh, xl);
    split_kernel<<<8192, 256>>>(to,   xh + (size_t)8192 * 1024, xl + (size_t)8192 * 1024);
    split_kernel<<<1024, 256>>>(Wq, wh,                         wl);
    split_kernel<<<1024, 256>>>(Wk, wh + (size_t)1024 * 1024,   wl + (size_t)1024 * 1024);
    split_kernel<<<1024, 256>>>(Wv, wh + (size_t)2048 * 1024,   wl + (size_t)2048 * 1024);

    dim3 pgrid(Hdim / 128, (Bsz * Fdim) / 128, 3);
    proj_kernel<<<pgrid, 256, sizeof(ProjSmem)>>>(bq, bk, bv);

    dim3 agrid(Fdim / 128, NH, Bsz);
    attn_kernel<<<agrid, 256, sizeof(AttnSmem)>>>(mask, out);
}

// round 10
// speedup vs baseline: 1.1218x; 1.1218x over previous
#include <cuda_runtime.h>
#include <cuda_fp16.h>
#include <math.h>
#include <stdint.h>

constexpr int Bsz  = 4;
constexpr int Fdim = 2048;
constexpr int Tdim = 2048;
constexpr int Hdim = 1024;
constexpr int NH   = 16;
constexpr int HS   = 64;

// ---------------------------------------------------------------------------
// fp16 split scratch in gmem
// ---------------------------------------------------------------------------
__device__ __half g_Xh[(size_t)16384 * 1024];   // rows 0-8191 from, 8192.. to
__device__ __half g_Xl[(size_t)16384 * 1024];
__device__ __half g_Wh[(size_t)3 * 1024 * 1024];
__device__ __half g_Wl[(size_t)3 * 1024 * 1024];
__device__ __half g_Qh[(size_t)Bsz * NH * Fdim * HS];   // Q pre-scaled by 1/8
__device__ __half g_Ql[(size_t)Bsz * NH * Fdim * HS];
__device__ __half g_Kh[(size_t)Bsz * NH * Tdim * HS];   // hi only
__device__ __half g_Vh[(size_t)Bsz * NH * Tdim * HS];   // hi only

// ---------------------------------------------------------------------------
// helpers
// ---------------------------------------------------------------------------
__device__ __forceinline__ uint32_t smem_u32(const void* p) {
    return (uint32_t)__cvta_generic_to_shared(p);
}
__device__ __forceinline__ void ldsm_x4(uint32_t* r, uint32_t a) {
    asm volatile("ldmatrix.sync.aligned.m8n8.x4.shared.b16 {%0,%1,%2,%3}, [%4];"
                 : "=r"(r[0]), "=r"(r[1]), "=r"(r[2]), "=r"(r[3]) : "r"(a));
}
__device__ __forceinline__ void ldsm_x4t(uint32_t* r, uint32_t a) {
    asm volatile("ldmatrix.sync.aligned.m8n8.x4.trans.shared.b16 {%0,%1,%2,%3}, [%4];"
                 : "=r"(r[0]), "=r"(r[1]), "=r"(r[2]), "=r"(r[3]) : "r"(a));
}
__device__ __forceinline__ void mma16816(float* c, const uint32_t* a, const uint32_t* b) {
    asm volatile(
        "mma.sync.aligned.m16n8k16.row.col.f32.f16.f16.f32 "
        "{%0,%1,%2,%3}, {%4,%5,%6,%7}, {%8,%9}, {%0,%1,%2,%3};"
        : "+f"(c[0]), "+f"(c[1]), "+f"(c[2]), "+f"(c[3])
        : "r"(a[0]), "r"(a[1]), "r"(a[2]), "r"(a[3]), "r"(b[0]), "r"(b[1]));
}
__device__ __forceinline__ void split_pack2(float x, float y, uint32_t& hi, uint32_t& lo) {
    __half hx = __float2half_rn(x);
    __half hy = __float2half_rn(y);
    __half2 hp = __halves2half2(hx, hy);
    hi = *reinterpret_cast<uint32_t*>(&hp);
    __half2 lp = __floats2half2_rn(x - __half2float(hx), y - __half2float(hy));
    lo = *reinterpret_cast<uint32_t*>(&lp);
}
__device__ __forceinline__ uint32_t pack2h(float x, float y) {
    __half2 hp = __floats2half2_rn(x, y);
    return *reinterpret_cast<uint32_t*>(&hp);
}
__device__ __forceinline__ void cp16(uint32_t s, const void* g) {
    asm volatile("cp.async.cg.shared.global [%0], [%1], 16;" :: "r"(s), "l"(g));
}
__device__ __forceinline__ void cp_commit() { asm volatile("cp.async.commit_group;"); }
template <int N> __device__ __forceinline__ void cp_wait() {
    asm volatile("cp.async.wait_group %0;" :: "n"(N));
}

// ---------------------------------------------------------------------------
// split pre-pass: fp32 -> (hi fp16, lo fp16)
// ---------------------------------------------------------------------------
__global__ __launch_bounds__(256) void split_kernel(
    const float* __restrict__ src, __half* __restrict__ h, __half* __restrict__ l)
{
    size_t i = ((size_t)blockIdx.x * 256 + threadIdx.x) * 4;
    float4 v = *(const float4*)(src + i);
    uint32_t h0, l0, h1, l1;
    split_pack2(v.x, v.y, h0, l0);
    split_pack2(v.z, v.w, h1, l1);
    uint2 hv = { h0, h1 }, lv = { l0, l1 };
    *(uint2*)(h + i) = hv;
    *(uint2*)(l + i) = lv;
}

// ---------------------------------------------------------------------------
// Projection GEMM: fp16 split 3-pass, 2-stage cp.async (R6-best structure).
// Block 128(M) x 128(N), K-step 32, 8 warps (warp tile 64x32).
// Q output: fp16 hi+lo scaled 1/8.  K/V output: fp16 hi only.
// ---------------------------------------------------------------------------
struct ProjSmem {
    __half AsH[2][128][40];
    __half AsL[2][128][40];
    __half BsH[2][32][136];
    __half BsL[2][32][136];
};

__global__ __launch_bounds__(256, 2) void proj_kernel(
    const float* __restrict__ bq, const float* __restrict__ bk,
    const float* __restrict__ bv)
{
    extern __shared__ char smem_raw[];
    ProjSmem& sm = *reinterpret_cast<ProjSmem*>(smem_raw);

    const int z = blockIdx.z;
    const __half* Ah = g_Xh + (z ? (size_t)8192 * 1024 : 0);
    const __half* Al = g_Xl + (z ? (size_t)8192 * 1024 : 0);
    const __half* Wh = g_Wh + (size_t)z * 1024 * 1024;
    const __half* Wl = g_Wl + (size_t)z * 1024 * 1024;
    const float* bias = (z == 0) ? bq : (z == 1) ? bk : bv;

    const int tid  = threadIdx.x;
    const int warp = tid >> 5;
    const int lane = tid & 31;
    const int g    = lane >> 2;
    const int tg   = lane & 3;

    const int m0 = blockIdx.y * 128;
    const int n0 = blockIdx.x * 128;
    const int wm = (warp >> 2) * 64;
    const int wn = (warp & 3) * 32;

    const int a_r = tid >> 1, a_c = (tid & 1) * 16;
    const int b_r = tid >> 3, b_c = (tid & 7) * 16;

    auto issue = [&](int st, int k0) {
        const __half* gah = Ah + (size_t)(m0 + a_r) * 1024 + k0 + a_c;
        const __half* gal = Al + (size_t)(m0 + a_r) * 1024 + k0 + a_c;
        cp16(smem_u32(&sm.AsH[st][a_r][a_c]),     gah);
        cp16(smem_u32(&sm.AsH[st][a_r][a_c + 8]), gah + 8);
        cp16(smem_u32(&sm.AsL[st][a_r][a_c]),     gal);
        cp16(smem_u32(&sm.AsL[st][a_r][a_c + 8]), gal + 8);
        const __half* gbh = Wh + (size_t)(k0 + b_r) * 1024 + n0 + b_c;
        const __half* gbl = Wl + (size_t)(k0 + b_r) * 1024 + n0 + b_c;
        cp16(smem_u32(&sm.BsH[st][b_r][b_c]),     gbh);
        cp16(smem_u32(&sm.BsH[st][b_r][b_c + 8]), gbh + 8);
        cp16(smem_u32(&sm.BsL[st][b_r][b_c]),     gbl);
        cp16(smem_u32(&sm.BsL[st][b_r][b_c + 8]), gbl + 8);
    };

    float acc[4][4][4] = {};

    issue(0, 0);
    cp_commit();

    const int ar = wm + (lane & 15);
    const int acol = (lane >> 4) * 8;
    const int l7 = lane & 7;
    const int khalf = (lane >> 3) & 1;
    const int nhalf = lane >> 4;

    for (int it = 0; it < 32; it++) {
        if (it + 1 < 32) { issue((it + 1) & 1, (it + 1) * 32); cp_commit(); cp_wait<1>(); }
        else             { cp_wait<0>(); }
        __syncthreads();
        const int st = it & 1;

#pragma unroll
        for (int kk = 0; kk < 32; kk += 16) {
            uint32_t bH[4][2], bL[4][2];
#pragma unroll
            for (int p = 0; p < 2; p++) {
                uint32_t r4[4];
                ldsm_x4t(r4, smem_u32(&sm.BsH[st][kk + khalf * 8 + l7][wn + p * 16 + nhalf * 8]));
                bH[2 * p][0] = r4[0]; bH[2 * p][1] = r4[1];
                bH[2 * p + 1][0] = r4[2]; bH[2 * p + 1][1] = r4[3];
                ldsm_x4t(r4, smem_u32(&sm.BsL[st][kk + khalf * 8 + l7][wn + p * 16 + nhalf * 8]));
                bL[2 * p][0] = r4[0]; bL[2 * p][1] = r4[1];
                bL[2 * p + 1][0] = r4[2]; bL[2 * p + 1][1] = r4[3];
            }
#pragma unroll
            for (int mi = 0; mi < 4; mi++) {
                uint32_t aH[4], aL[4];
                ldsm_x4(aH, smem_u32(&sm.AsH[st][ar + mi * 16][kk + acol]));
                ldsm_x4(aL, smem_u32(&sm.AsL[st][ar + mi * 16][kk + acol]));
#pragma unroll
                for (int ni = 0; ni < 4; ni++) {
                    mma16816(acc[mi][ni], aH, bH[ni]);
                    mma16816(acc[mi][ni], aH, bL[ni]);
                    mma16816(acc[mi][ni], aL, bH[ni]);
                }
            }
        }
        __syncthreads();
    }

    // epilogue
#pragma unroll
    for (int ni = 0; ni < 4; ni++) {
        const int col = n0 + wn + ni * 8 + tg * 2;
        const int head = col >> 6;
        const int d = col & 63;
        float2 b2 = *(const float2*)&bias[col];
#pragma unroll
        for (int mi = 0; mi < 4; mi++) {
#pragma unroll
            for (int half = 0; half < 2; half++) {
                int m  = m0 + wm + mi * 16 + g + half * 8;
                int bi = m >> 11, si = m & 2047;
                size_t idx = (((size_t)bi * NH + head) * 2048 + si) * HS + d;
                float x = acc[mi][ni][2 * half]     + b2.x;
                float y = acc[mi][ni][2 * half + 1] + b2.y;
                if (z == 0) {
                    uint32_t hi, lo;
                    split_pack2(x * 0.125f, y * 0.125f, hi, lo);
                    *(uint32_t*)&g_Qh[idx] = hi;
                    *(uint32_t*)&g_Ql[idx] = lo;
                } else if (z == 1) {
                    *(uint32_t*)&g_Kh[idx] = pack2h(x, y);
                } else {
                    *(uint32_t*)&g_Vh[idx] = pack2h(x, y);
                }
            }
        }
    }
}

// ---------------------------------------------------------------------------
// Flash attention: fp16, 2-pass (K/V hi only), 2-stage cp.async.
// Block 128 F-rows x 64 T-tile, 8 warps (one m16 band each).
// ---------------------------------------------------------------------------
struct AttnSmem {
    __half KH[2][64][72];
    __half VH[2][64][72];
};

__global__ __launch_bounds__(256, 2) void attn_kernel(
    const float* __restrict__ mask,   // [B, F, T]
    float* __restrict__ out)          // [B, F, NH, HS]
{
    extern __shared__ char smem_raw[];
    AttnSmem& sm = *reinterpret_cast<AttnSmem*>(smem_raw);

    const int tid  = threadIdx.x;
    const int warp = tid >> 5;
    const int lane = tid & 31;
    const int g    = lane >> 2;
    const int tg   = lane & 3;

    const int f0 = blockIdx.x * 128;
    const int n  = blockIdx.y;
    const int b  = blockIdx.z;
    const size_t hb = (size_t)b * NH + n;

    const __half* Qh = g_Qh + (hb * Fdim + f0 + warp * 16) * HS;
    const __half* Ql = g_Ql + (hb * Fdim + f0 + warp * 16) * HS;
    const __half* Kh = g_Kh + hb * Tdim * HS;
    const __half* Vh = g_Vh + hb * Tdim * HS;
    const float* Mw = mask + ((size_t)b * Fdim + f0 + warp * 16) * Tdim;

    // Q fragments (already scaled by 1/8)
    uint32_t qH[4][4], qL[4][4];
#pragma unroll
    for (int kc = 0; kc < 4; kc++) {
        qH[kc][0] = *(const uint32_t*)(Qh + (size_t)g * HS + kc * 16 + tg * 2);
        qH[kc][1] = *(const uint32_t*)(Qh + (size_t)(g + 8) * HS + kc * 16 + tg * 2);
        qH[kc][2] = *(const uint32_t*)(Qh + (size_t)g * HS + kc * 16 + 8 + tg * 2);
        qH[kc][3] = *(const uint32_t*)(Qh + (size_t)(g + 8) * HS + kc * 16 + 8 + tg * 2);
        qL[kc][0] = *(const uint32_t*)(Ql + (size_t)g * HS + kc * 16 + tg * 2);
        qL[kc][1] = *(const uint32_t*)(Ql + (size_t)(g + 8) * HS + kc * 16 + tg * 2);
        qL[kc][2] = *(const uint32_t*)(Ql + (size_t)g * HS + kc * 16 + 8 + tg * 2);
        qL[kc][3] = *(const uint32_t*)(Ql + (size_t)(g + 8) * HS + kc * 16 + 8 + tg * 2);
    }

    const int ld_r = tid >> 2;
    const int ld_c = (tid & 3) * 16;

    auto issue = [&](int st, int t0) {
        const size_t go = (size_t)(t0 + ld_r) * HS + ld_c;
        cp16(smem_u32(&sm.KH[st][ld_r][ld_c]),     Kh + go);
        cp16(smem_u32(&sm.KH[st][ld_r][ld_c + 8]), Kh + go + 8);
        cp16(smem_u32(&sm.VH[st][ld_r][ld_c]),     Vh + go);
        cp16(smem_u32(&sm.VH[st][ld_r][ld_c + 8]), Vh + go + 8);
    };

    float o[8][4] = {};
    float mrow0 = -1e30f, mrow1 = -1e30f, l0 = 0.f, l1 = 0.f;

    issue(0, 0);
    cp_commit();

    const int l7 = lane & 7;
    const int half8 = (lane >> 3) & 1;
    const int quad  = lane >> 4;

    for (int it = 0; it < 32; it++) {
        const int t0 = it * 64;
        if (it + 1 < 32) { issue((it + 1) & 1, t0 + 64); cp_commit(); cp_wait<1>(); }
        else             { cp_wait<0>(); }
        __syncthreads();
        const int st = it & 1;

        // S = Q K^T  (2-pass: qh*kh + ql*kh)
        float s[8][4];
#pragma unroll
        for (int ni = 0; ni < 8; ni++)
            s[ni][0] = s[ni][1] = s[ni][2] = s[ni][3] = 0.f;

#pragma unroll
        for (int np = 0; np < 4; np++) {
            const int krow = np * 16 + quad * 8 + l7;
#pragma unroll
            for (int kc = 0; kc < 4; kc++) {
                uint32_t k4h[4];
                ldsm_x4(k4h, smem_u32(&sm.KH[st][krow][kc * 16 + half8 * 8]));
                mma16816(s[2 * np],     qH[kc], k4h);
                mma16816(s[2 * np],     qL[kc], k4h);
                mma16816(s[2 * np + 1], qH[kc], k4h + 2);
                mma16816(s[2 * np + 1], qL[kc], k4h + 2);
            }
        }

        // mask adder
#pragma unroll
        for (int ni = 0; ni < 8; ni++) {
            float2 mm0 = *(const float2*)&Mw[(size_t)g * Tdim + t0 + ni * 8 + tg * 2];
            float2 mm1 = *(const float2*)&Mw[(size_t)(g + 8) * Tdim + t0 + ni * 8 + tg * 2];
            s[ni][0] += (1.f - mm0.x) * (-10000.f);
            s[ni][1] += (1.f - mm0.y) * (-10000.f);
            s[ni][2] += (1.f - mm1.x) * (-10000.f);
            s[ni][3] += (1.f - mm1.y) * (-10000.f);
        }

        // online softmax
        float rmax0 = -1e30f, rmax1 = -1e30f;
#pragma unroll
        for (int ni = 0; ni < 8; ni++) {
            rmax0 = fmaxf(rmax0, fmaxf(s[ni][0], s[ni][1]));
            rmax1 = fmaxf(rmax1, fmaxf(s[ni][2], s[ni][3]));
        }
        rmax0 = fmaxf(rmax0, __shfl_xor_sync(0xffffffffu, rmax0, 1));
        rmax0 = fmaxf(rmax0, __shfl_xor_sync(0xffffffffu, rmax0, 2));
        rmax1 = fmaxf(rmax1, __shfl_xor_sync(0xffffffffu, rmax1, 1));
        rmax1 = fmaxf(rmax1, __shfl_xor_sync(0xffffffffu, rmax1, 2));

        float mnew0 = fmaxf(mrow0, rmax0);
        float mnew1 = fmaxf(mrow1, rmax1);
        float esc0 = __expf(mrow0 - mnew0);
        float esc1 = __expf(mrow1 - mnew1);
        mrow0 = mnew0;  mrow1 = mnew1;

        float rs0 = 0.f, rs1 = 0.f;
#pragma unroll
        for (int ni = 0; ni < 8; ni++) {
            s[ni][0] = __expf(s[ni][0] - mnew0);
            s[ni][1] = __expf(s[ni][1] - mnew0);
            s[ni][2] = __expf(s[ni][2] - mnew1);
            s[ni][3] = __expf(s[ni][3] - mnew1);
            rs0 += s[ni][0] + s[ni][1];
            rs1 += s[ni][2] + s[ni][3];
        }
        rs0 += __shfl_xor_sync(0xffffffffu, rs0, 1);
        rs0 += __shfl_xor_sync(0xffffffffu, rs0, 2);
        rs1 += __shfl_xor_sync(0xffffffffu, rs1, 1);
        rs1 += __shfl_xor_sync(0xffffffffu, rs1, 2);

        l0 = l0 * esc0 + rs0;
        l1 = l1 * esc1 + rs1;
#pragma unroll
        for (int di = 0; di < 8; di++) {
            o[di][0] *= esc0;  o[di][1] *= esc0;
            o[di][2] *= esc1;  o[di][3] *= esc1;
        }

        // O += P V  (2-pass: ph*vh + pl*vh)
#pragma unroll
        for (int kc = 0; kc < 4; kc++) {
            uint32_t pH[4], pL[4];
            split_pack2(s[2 * kc][0],     s[2 * kc][1],     pH[0], pL[0]);
            split_pack2(s[2 * kc][2],     s[2 * kc][3],     pH[1], pL[1]);
            split_pack2(s[2 * kc + 1][0], s[2 * kc + 1][1], pH[2], pL[2]);
            split_pack2(s[2 * kc + 1][2], s[2 * kc + 1][3], pH[3], pL[3]);
            const int vrow = kc * 16 + half8 * 8 + l7;
#pragma unroll
            for (int dp = 0; dp < 4; dp++) {
                uint32_t v4h[4];
                ldsm_x4t(v4h, smem_u32(&sm.VH[st][vrow][dp * 16 + quad * 8]));
                mma16816(o[2 * dp],     pH, v4h);
                mma16816(o[2 * dp],     pL, v4h);
                mma16816(o[2 * dp + 1], pH, v4h + 2);
                mma16816(o[2 * dp + 1], pL, v4h + 2);
            }
        }
        __syncthreads();
    }

    // epilogue
    const float inv0 = 1.f / l0;
    const float inv1 = 1.f / l1;
    const int f = f0 + warp * 16 + g;
    float* orow0 = out + (((size_t)b * Fdim + f) * NH + n) * HS;
    float* orow1 = out + (((size_t)b * Fdim + f + 8) * NH + n) * HS;
#pragma unroll
    for (int di = 0; di < 8; di++) {
        float2 r0 = { o[di][0] * inv0, o[di][1] * inv0 };
        float2 r1 = { o[di][2] * inv1, o[di][3] * inv1 };
        *(float2*)&orow0[di * 8 + tg * 2] = r0;
        *(float2*)&orow1[di * 8 + tg * 2] = r1;
    }
}

// ---------------------------------------------------------------------------
extern "C" void kernel_launch(void* const* d_in, const int* in_sizes, int n_in,
                              void* d_out, int out_size)
{
    const float* from = (const float*)d_in[0];
    const float* to   = (const float*)d_in[1];
    const float* mask = (const float*)d_in[2];
    const float* Wq   = (const float*)d_in[3];
    const float* bq   = (const float*)d_in[4];
    const float* Wk   = (const float*)d_in[5];
    const float* bk   = (const float*)d_in[6];
    const float* Wv   = (const float*)d_in[7];
    const float* bv   = (const float*)d_in[8];
    float* out = (float*)d_out;

    cudaFuncSetAttribute(proj_kernel, cudaFuncAttributeMaxDynamicSharedMemorySize,
                         (int)sizeof(ProjSmem));
    cudaFuncSetAttribute(attn_kernel, cudaFuncAttributeMaxDynamicSharedMemorySize,
                         (int)sizeof(AttnSmem));

    __half *xh, *xl, *wh, *wl;
    cudaGetSymbolAddress((void**)&xh, g_Xh);
    cudaGetSymbolAddress((void**)&xl, g_Xl);
    cudaGetSymbolAddress((void**)&wh, g_Wh);
    cudaGetSymbolAddress((void**)&wl, g_Wl);

    split_kernel<<<8192, 256>>>(from, xh, xl);
    split_kernel<<<8192, 256>>>(to,   xh + (size_t)8192 * 1024, xl + (size_t)8192 * 1024);
    split_kernel<<<1024, 256>>>(Wq, wh,                         wl);
    split_kernel<<<1024, 256>>>(Wk, wh + (size_t)1024 * 1024,   wl + (size_t)1024 * 1024);
    split_kernel<<<1024, 256>>>(Wv, wh + (size_t)2048 * 1024,   wl + (size_t)2048 * 1024);

    dim3 pgrid(Hdim / 128, (Bsz * Fdim) / 128, 3);
    proj_kernel<<<pgrid, 256, sizeof(ProjSmem)>>>(bq, bk, bv);

    dim3 agrid(Fdim / 128, NH, Bsz);
    attn_kernel<<<agrid, 256, sizeof(AttnSmem)>>>(mask, out);
}

// round 11
// speedup vs baseline: 1.1237x; 1.0017x over previous
#include <cuda_runtime.h>
#include <cuda_fp16.h>
#include <math.h>
#include <stdint.h>

constexpr int Bsz  = 4;
constexpr int Fdim = 2048;
constexpr int Tdim = 2048;
constexpr int Hdim = 1024;
constexpr int NH   = 16;
constexpr int HS   = 64;

// ---------------------------------------------------------------------------
// fp16 split scratch in gmem
// ---------------------------------------------------------------------------
__device__ __half g_Xh[(size_t)16384 * 1024];   // rows 0-8191 from, 8192.. to
__device__ __half g_Xl[(size_t)16384 * 1024];
__device__ __half g_Wh[(size_t)3 * 1024 * 1024];
__device__ __half g_Wl[(size_t)3 * 1024 * 1024];
__device__ __half g_Qh[(size_t)Bsz * NH * Fdim * HS];   // Q pre-scaled by 1/8
__device__ __half g_Ql[(size_t)Bsz * NH * Fdim * HS];
__device__ __half g_Kh[(size_t)Bsz * NH * Tdim * HS];   // hi only
__device__ __half g_Vh[(size_t)Bsz * NH * Tdim * HS];   // hi only

// ---------------------------------------------------------------------------
// helpers
// ---------------------------------------------------------------------------
__device__ __forceinline__ uint32_t smem_u32(const void* p) {
    return (uint32_t)__cvta_generic_to_shared(p);
}
__device__ __forceinline__ void ldsm_x4(uint32_t* r, uint32_t a) {
    asm volatile("ldmatrix.sync.aligned.m8n8.x4.shared.b16 {%0,%1,%2,%3}, [%4];"
                 : "=r"(r[0]), "=r"(r[1]), "=r"(r[2]), "=r"(r[3]) : "r"(a));
}
__device__ __forceinline__ void ldsm_x4t(uint32_t* r, uint32_t a) {
    asm volatile("ldmatrix.sync.aligned.m8n8.x4.trans.shared.b16 {%0,%1,%2,%3}, [%4];"
                 : "=r"(r[0]), "=r"(r[1]), "=r"(r[2]), "=r"(r[3]) : "r"(a));
}
__device__ __forceinline__ void mma16816(float* c, const uint32_t* a, const uint32_t* b) {
    asm volatile(
        "mma.sync.aligned.m16n8k16.row.col.f32.f16.f16.f32 "
        "{%0,%1,%2,%3}, {%4,%5,%6,%7}, {%8,%9}, {%0,%1,%2,%3};"
        : "+f"(c[0]), "+f"(c[1]), "+f"(c[2]), "+f"(c[3])
        : "r"(a[0]), "r"(a[1]), "r"(a[2]), "r"(a[3]), "r"(b[0]), "r"(b[1]));
}
__device__ __forceinline__ void split_pack2(float x, float y, uint32_t& hi, uint32_t& lo) {
    __half hx = __float2half_rn(x);
    __half hy = __float2half_rn(y);
    __half2 hp = __halves2half2(hx, hy);
    hi = *reinterpret_cast<uint32_t*>(&hp);
    __half2 lp = __floats2half2_rn(x - __half2float(hx), y - __half2float(hy));
    lo = *reinterpret_cast<uint32_t*>(&lp);
}
__device__ __forceinline__ uint32_t pack2h(float x, float y) {
    __half2 hp = __floats2half2_rn(x, y);
    return *reinterpret_cast<uint32_t*>(&hp);
}
__device__ __forceinline__ void cp16(uint32_t s, const void* g) {
    asm volatile("cp.async.cg.shared.global [%0], [%1], 16;" :: "r"(s), "l"(g));
}
__device__ __forceinline__ void cp_commit() { asm volatile("cp.async.commit_group;"); }
template <int N> __device__ __forceinline__ void cp_wait() {
    asm volatile("cp.async.wait_group %0;" :: "n"(N));
}

// ---------------------------------------------------------------------------
// split pre-pass: fp32 -> (hi fp16, lo fp16)
// ---------------------------------------------------------------------------
__global__ __launch_bounds__(256) void split_kernel(
    const float* __restrict__ src, __half* __restrict__ h, __half* __restrict__ l)
{
    size_t i = ((size_t)blockIdx.x * 256 + threadIdx.x) * 4;
    float4 v = *(const float4*)(src + i);
    uint32_t h0, l0, h1, l1;
    split_pack2(v.x, v.y, h0, l0);
    split_pack2(v.z, v.w, h1, l1);
    uint2 hv = { h0, h1 }, lv = { l0, l1 };
    *(uint2*)(h + i) = hv;
    *(uint2*)(l + i) = lv;
}

// ---------------------------------------------------------------------------
// Projection GEMM: fp16 split 3-pass, 2-stage cp.async (R6-best structure).
// Block 128(M) x 128(N), K-step 32, 8 warps (warp tile 64x32).
// Q output: fp16 hi+lo scaled 1/8.  K/V output: fp16 hi only.
// ---------------------------------------------------------------------------
struct ProjSmem {
    __half AsH[2][128][40];
    __half AsL[2][128][40];
    __half BsH[2][32][136];
    __half BsL[2][32][136];
};

__global__ __launch_bounds__(256, 2) void proj_kernel(
    const float* __restrict__ bq, const float* __restrict__ bk,
    const float* __restrict__ bv)
{
    extern __shared__ char smem_raw[];
    ProjSmem& sm = *reinterpret_cast<ProjSmem*>(smem_raw);

    const int z = blockIdx.z;
    const __half* Ah = g_Xh + (z ? (size_t)8192 * 1024 : 0);
    const __half* Al = g_Xl + (z ? (size_t)8192 * 1024 : 0);
    const __half* Wh = g_Wh + (size_t)z * 1024 * 1024;
    const __half* Wl = g_Wl + (size_t)z * 1024 * 1024;
    const float* bias = (z == 0) ? bq : (z == 1) ? bk : bv;

    const int tid  = threadIdx.x;
    const int warp = tid >> 5;
    const int lane = tid & 31;
    const int g    = lane >> 2;
    const int tg   = lane & 3;

    const int m0 = blockIdx.y * 128;
    const int n0 = blockIdx.x * 128;
    const int wm = (warp >> 2) * 64;
    const int wn = (warp & 3) * 32;

    const int a_r = tid >> 1, a_c = (tid & 1) * 16;
    const int b_r = tid >> 3, b_c = (tid & 7) * 16;

    auto issue = [&](int st, int k0) {
        const __half* gah = Ah + (size_t)(m0 + a_r) * 1024 + k0 + a_c;
        const __half* gal = Al + (size_t)(m0 + a_r) * 1024 + k0 + a_c;
        cp16(smem_u32(&sm.AsH[st][a_r][a_c]),     gah);
        cp16(smem_u32(&sm.AsH[st][a_r][a_c + 8]), gah + 8);
        cp16(smem_u32(&sm.AsL[st][a_r][a_c]),     gal);
        cp16(smem_u32(&sm.AsL[st][a_r][a_c + 8]), gal + 8);
        const __half* gbh = Wh + (size_t)(k0 + b_r) * 1024 + n0 + b_c;
        const __half* gbl = Wl + (size_t)(k0 + b_r) * 1024 + n0 + b_c;
        cp16(smem_u32(&sm.BsH[st][b_r][b_c]),     gbh);
        cp16(smem_u32(&sm.BsH[st][b_r][b_c + 8]), gbh + 8);
        cp16(smem_u32(&sm.BsL[st][b_r][b_c]),     gbl);
        cp16(smem_u32(&sm.BsL[st][b_r][b_c + 8]), gbl + 8);
    };

    float acc[4][4][4] = {};

    issue(0, 0);
    cp_commit();

    const int ar = wm + (lane & 15);
    const int acol = (lane >> 4) * 8;
    const int l7 = lane & 7;
    const int khalf = (lane >> 3) & 1;
    const int nhalf = lane >> 4;

    for (int it = 0; it < 32; it++) {
        if (it + 1 < 32) { issue((it + 1) & 1, (it + 1) * 32); cp_commit(); cp_wait<1>(); }
        else             { cp_wait<0>(); }
        __syncthreads();
        const int st = it & 1;

#pragma unroll
        for (int kk = 0; kk < 32; kk += 16) {
            uint32_t bH[4][2], bL[4][2];
#pragma unroll
            for (int p = 0; p < 2; p++) {
                uint32_t r4[4];
                ldsm_x4t(r4, smem_u32(&sm.BsH[st][kk + khalf * 8 + l7][wn + p * 16 + nhalf * 8]));
                bH[2 * p][0] = r4[0]; bH[2 * p][1] = r4[1];
                bH[2 * p + 1][0] = r4[2]; bH[2 * p + 1][1] = r4[3];
                ldsm_x4t(r4, smem_u32(&sm.BsL[st][kk + khalf * 8 + l7][wn + p * 16 + nhalf * 8]));
                bL[2 * p][0] = r4[0]; bL[2 * p][1] = r4[1];
                bL[2 * p + 1][0] = r4[2]; bL[2 * p + 1][1] = r4[3];
            }
#pragma unroll
            for (int mi = 0; mi < 4; mi++) {
                uint32_t aH[4], aL[4];
                ldsm_x4(aH, smem_u32(&sm.AsH[st][ar + mi * 16][kk + acol]));
                ldsm_x4(aL, smem_u32(&sm.AsL[st][ar + mi * 16][kk + acol]));
#pragma unroll
                for (int ni = 0; ni < 4; ni++) {
                    mma16816(acc[mi][ni], aH, bH[ni]);
                    mma16816(acc[mi][ni], aH, bL[ni]);
                    mma16816(acc[mi][ni], aL, bH[ni]);
                }
            }
        }
        __syncthreads();
    }

    // epilogue
#pragma unroll
    for (int ni = 0; ni < 4; ni++) {
        const int col = n0 + wn + ni * 8 + tg * 2;
        const int head = col >> 6;
        const int d = col & 63;
        float2 b2 = *(const float2*)&bias[col];
#pragma unroll
        for (int mi = 0; mi < 4; mi++) {
#pragma unroll
            for (int half = 0; half < 2; half++) {
                int m  = m0 + wm + mi * 16 + g + half * 8;
                int bi = m >> 11, si = m & 2047;
                size_t idx = (((size_t)bi * NH + head) * 2048 + si) * HS + d;
                float x = acc[mi][ni][2 * half]     + b2.x;
                float y = acc[mi][ni][2 * half + 1] + b2.y;
                if (z == 0) {
                    uint32_t hi, lo;
                    split_pack2(x * 0.125f, y * 0.125f, hi, lo);
                    *(uint32_t*)&g_Qh[idx] = hi;
                    *(uint32_t*)&g_Ql[idx] = lo;
                } else if (z == 1) {
                    *(uint32_t*)&g_Kh[idx] = pack2h(x, y);
                } else {
                    *(uint32_t*)&g_Vh[idx] = pack2h(x, y);
                }
            }
        }
    }
}

// ---------------------------------------------------------------------------
// Flash attention: fp16, 2-pass (K/V hi only), 2-stage cp.async.
// Block 128 F-rows x 64 T-tile, 8 warps (one m16 band each).
// ---------------------------------------------------------------------------
struct AttnSmem {
    __half KH[2][64][72];
    __half VH[2][64][72];
};

__global__ __launch_bounds__(256, 2) void attn_kernel(
    const float* __restrict__ mask,   // [B, F, T]
    float* __restrict__ out)          // [B, F, NH, HS]
{
    extern __shared__ char smem_raw[];
    AttnSmem& sm = *reinterpret_cast<AttnSmem*>(smem_raw);

    const int tid  = threadIdx.x;
    const int warp = tid >> 5;
    const int lane = tid & 31;
    const int g    = lane >> 2;
    const int tg   = lane & 3;

    const int f0 = blockIdx.x * 128;
    const int n  = blockIdx.y;
    const int b  = blockIdx.z;
    const size_t hb = (size_t)b * NH + n;

    const __half* Qh = g_Qh + (hb * Fdim + f0 + warp * 16) * HS;
    const __half* Ql = g_Ql + (hb * Fdim + f0 + warp * 16) * HS;
    const __half* Kh = g_Kh + hb * Tdim * HS;
    const __half* Vh = g_Vh + hb * Tdim * HS;
    const float* Mw = mask + ((size_t)b * Fdim + f0 + warp * 16) * Tdim;

    // Q fragments (already scaled by 1/8)
    uint32_t qH[4][4], qL[4][4];
#pragma unroll
    for (int kc = 0; kc < 4; kc++) {
        qH[kc][0] = *(const uint32_t*)(Qh + (size_t)g * HS + kc * 16 + tg * 2);
        qH[kc][1] = *(const uint32_t*)(Qh + (size_t)(g + 8) * HS + kc * 16 + tg * 2);
        qH[kc][2] = *(const uint32_t*)(Qh + (size_t)g * HS + kc * 16 + 8 + tg * 2);
        qH[kc][3] = *(const uint32_t*)(Qh + (size_t)(g + 8) * HS + kc * 16 + 8 + tg * 2);
        qL[kc][0] = *(const uint32_t*)(Ql + (size_t)g * HS + kc * 16 + tg * 2);
        qL[kc][1] = *(const uint32_t*)(Ql + (size_t)(g + 8) * HS + kc * 16 + tg * 2);
        qL[kc][2] = *(const uint32_t*)(Ql + (size_t)g * HS + kc * 16 + 8 + tg * 2);
        qL[kc][3] = *(const uint32_t*)(Ql + (size_t)(g + 8) * HS + kc * 16 + 8 + tg * 2);
    }

    const int ld_r = tid >> 2;
    const int ld_c = (tid & 3) * 16;

    auto issue = [&](int st, int t0) {
        const size_t go = (size_t)(t0 + ld_r) * HS + ld_c;
        cp16(smem_u32(&sm.KH[st][ld_r][ld_c]),     Kh + go);
        cp16(smem_u32(&sm.KH[st][ld_r][ld_c + 8]), Kh + go + 8);
        cp16(smem_u32(&sm.VH[st][ld_r][ld_c]),     Vh + go);
        cp16(smem_u32(&sm.VH[st][ld_r][ld_c + 8]), Vh + go + 8);
    };

    float o[8][4] = {};
    float mrow0 = -1e30f, mrow1 = -1e30f, l0 = 0.f, l1 = 0.f;

    issue(0, 0);
    cp_commit();

    const int l7 = lane & 7;
    const int half8 = (lane >> 3) & 1;
    const int quad  = lane >> 4;

    for (int it = 0; it < 32; it++) {
        const int t0 = it * 64;
        if (it + 1 < 32) { issue((it + 1) & 1, t0 + 64); cp_commit(); cp_wait<1>(); }
        else             { cp_wait<0>(); }
        __syncthreads();
        const int st = it & 1;

        // S = Q K^T  (2-pass: qh*kh + ql*kh)
        float s[8][4];
#pragma unroll
        for (int ni = 0; ni < 8; ni++)
            s[ni][0] = s[ni][1] = s[ni][2] = s[ni][3] = 0.f;

#pragma unroll
        for (int np = 0; np < 4; np++) {
            const int krow = np * 16 + quad * 8 + l7;
#pragma unroll
            for (int kc = 0; kc < 4; kc++) {
                uint32_t k4h[4];
                ldsm_x4(k4h, smem_u32(&sm.KH[st][krow][kc * 16 + half8 * 8]));
                mma16816(s[2 * np],     qH[kc], k4h);
                mma16816(s[2 * np],     qL[kc], k4h);
                mma16816(s[2 * np + 1], qH[kc], k4h + 2);
                mma16816(s[2 * np + 1], qL[kc], k4h + 2);
            }
        }

        // mask adder
#pragma unroll
        for (int ni = 0; ni < 8; ni++) {
            float2 mm0 = *(const float2*)&Mw[(size_t)g * Tdim + t0 + ni * 8 + tg * 2];
            float2 mm1 = *(const float2*)&Mw[(size_t)(g + 8) * Tdim + t0 + ni * 8 + tg * 2];
            s[ni][0] += (1.f - mm0.x) * (-10000.f);
            s[ni][1] += (1.f - mm0.y) * (-10000.f);
            s[ni][2] += (1.f - mm1.x) * (-10000.f);
            s[ni][3] += (1.f - mm1.y) * (-10000.f);
        }

        // online softmax
        float rmax0 = -1e30f, rmax1 = -1e30f;
#pragma unroll
        for (int ni = 0; ni < 8; ni++) {
            rmax0 = fmaxf(rmax0, fmaxf(s[ni][0], s[ni][1]));
            rmax1 = fmaxf(rmax1, fmaxf(s[ni][2], s[ni][3]));
        }
        rmax0 = fmaxf(rmax0, __shfl_xor_sync(0xffffffffu, rmax0, 1));
        rmax0 = fmaxf(rmax0, __shfl_xor_sync(0xffffffffu, rmax0, 2));
        rmax1 = fmaxf(rmax1, __shfl_xor_sync(0xffffffffu, rmax1, 1));
        rmax1 = fmaxf(rmax1, __shfl_xor_sync(0xffffffffu, rmax1, 2));

        float mnew0 = fmaxf(mrow0, rmax0);
        float mnew1 = fmaxf(mrow1, rmax1);
        float esc0 = __expf(mrow0 - mnew0);
        float esc1 = __expf(mrow1 - mnew1);
        mrow0 = mnew0;  mrow1 = mnew1;

        float rs0 = 0.f, rs1 = 0.f;
#pragma unroll
        for (int ni = 0; ni < 8; ni++) {
            s[ni][0] = __expf(s[ni][0] - mnew0);
            s[ni][1] = __expf(s[ni][1] - mnew0);
            s[ni][2] = __expf(s[ni][2] - mnew1);
            s[ni][3] = __expf(s[ni][3] - mnew1);
            rs0 += s[ni][0] + s[ni][1];
            rs1 += s[ni][2] + s[ni][3];
        }
        rs0 += __shfl_xor_sync(0xffffffffu, rs0, 1);
        rs0 += __shfl_xor_sync(0xffffffffu, rs0, 2);
        rs1 += __shfl_xor_sync(0xffffffffu, rs1, 1);
        rs1 += __shfl_xor_sync(0xffffffffu, rs1, 2);

        l0 = l0 * esc0 + rs0;
        l1 = l1 * esc1 + rs1;
#pragma unroll
        for (int di = 0; di < 8; di++) {
            o[di][0] *= esc0;  o[di][1] *= esc0;
            o[di][2] *= esc1;  o[di][3] *= esc1;
        }

        // O += P V  (2-pass: ph*vh + pl*vh)
#pragma unroll
        for (int kc = 0; kc < 4; kc++) {
            uint32_t pH[4], pL[4];
            split_pack2(s[2 * kc][0],     s[2 * kc][1],     pH[0], pL[0]);
            split_pack2(s[2 * kc][2],     s[2 * kc][3],     pH[1], pL[1]);
            split_pack2(s[2 * kc + 1][0], s[2 * kc + 1][1], pH[2], pL[2]);
            split_pack2(s[2 * kc + 1][2], s[2 * kc + 1][3], pH[3], pL[3]);
            const int vrow = kc * 16 + half8 * 8 + l7;
#pragma unroll
            for (int dp = 0; dp < 4; dp++) {
                uint32_t v4h[4];
                ldsm_x4t(v4h, smem_u32(&sm.VH[st][vrow][dp * 16 + quad * 8]));
                mma16816(o[2 * dp],     pH, v4h);
                mma16816(o[2 * dp],     pL, v4h);
                mma16816(o[2 * dp + 1], pH, v4h + 2);
                mma16816(o[2 * dp + 1], pL, v4h + 2);
            }
        }
        __syncthreads();
    }

    // epilogue
    const float inv0 = 1.f / l0;
    const float inv1 = 1.f / l1;
    const int f = f0 + warp * 16 + g;
    float* orow0 = out + (((size_t)b * Fdim + f) * NH + n) * HS;
    float* orow1 = out + (((size_t)b * Fdim + f + 8) * NH + n) * HS;
#pragma unroll
    for (int di = 0; di < 8; di++) {
        float2 r0 = { o[di][0] * inv0, o[di][1] * inv0 };
        float2 r1 = { o[di][2] * inv1, o[di][3] * inv1 };
        *(float2*)&orow0[di * 8 + tg * 2] = r0;
        *(float2*)&orow1[di * 8 + tg * 2] = r1;
    }
}

// ---------------------------------------------------------------------------
extern "C" void kernel_launch(void* const* d_in, const int* in_sizes, int n_in,
                              void* d_out, int out_size)
{
    const float* from = (const float*)d_in[0];
    const float* to   = (const float*)d_in[1];
    const float* mask = (const float*)d_in[2];
    const float* Wq   = (const float*)d_in[3];
    const float* bq   = (const float*)d_in[4];
    const float* Wk   = (const float*)d_in[5];
    const float* bk   = (const float*)d_in[6];
    const float* Wv   = (const float*)d_in[7];
    const float* bv   = (const float*)d_in[8];
    float* out = (float*)d_out;

    cudaFuncSetAttribute(proj_kernel, cudaFuncAttributeMaxDynamicSharedMemorySize,
                         (int)sizeof(ProjSmem));
    cudaFuncSetAttribute(attn_kernel, cudaFuncAttributeMaxDynamicSharedMemorySize,
                         (int)sizeof(AttnSmem));

    __half *xh, *xl, *wh, *wl;
    cudaGetSymbolAddress((void**)&xh, g_Xh);
    cudaGetSymbolAddress((void**)&xl, g_Xl);
    cudaGetSymbolAddress((void**)&wh, g_Wh);
    cudaGetSymbolAddress((void**)&wl, g_Wl);

    split_kernel<<<8192, 256>>>(from, xh, xl);
    split_kernel<<<8192, 256>>>(to,   xh + (size_t)8192 * 1024, xl + (size_t)8192 * 1024);
    split_kernel<<<1024, 256>>>(Wq, wh,                         wl);
    split_kernel<<<1024, 256>>>(Wk, wh + (size_t)1024 * 1024,   wl + (size_t)1024 * 1024);
    split_kernel<<<1024, 256>>>(Wv, wh + (size_t)2048 * 1024,   wl + (size_t)2048 * 1024);

    dim3 pgrid(Hdim / 128, (Bsz * Fdim) / 128, 3);
    proj_kernel<<<pgrid, 256, sizeof(ProjSmem)>>>(bq, bk, bv);

    dim3 agrid(Fdim / 128, NH, Bsz);
    attn_kernel<<<agrid, 256, sizeof(AttnSmem)>>>(mask, out);
}